// round 3
// baseline (speedup 1.0000x reference)
#include <cuda_runtime.h>
#include <cstdint>

#define T_TOK 8192
#define DIM   1024
#define HID   2752
#define NE    8
#define TOPK  2

#define BM 128
#define BN 128
#define BK 32
#define SROW (BK + 4)                 // 36 floats per smem row (conflict-free)
#define SA_F (BM * SROW)              // 4608 floats
#define SB_F (BN * SROW)              // 4608 floats
#define ST1_F (SA_F + 2 * SB_F)       // 13824 floats per stage (A + B1 + B3)
#define ST2_F (SA_F + SB_F)           // 9216 floats per stage
#define SMEM1 (2 * ST1_F * 4 + 512)   // 111104 B
#define SMEM2 (2 * ST2_F * 4)         // 73728 B

#define NT1 ((HID + BN - 1) / BN)     // 22 (21 full + 64 tail)
#define NT2 (DIM / BN)                // 8
#define NIT1 (DIM / BK)               // 32
#define NIT2 (HID / BK)               // 86

// ---------------- device scratch (no runtime allocation allowed) -------------
__device__ int   g_counts[NE];
__device__ int   g_offsets[NE + 1];
__device__ int   g_fill[NE];
__device__ int   g_topk_idx[T_TOK * TOPK];
__device__ float g_topk_w[T_TOK * TOPK];
__device__ int   g_perm[T_TOK * TOPK];
__device__ float g_coef[T_TOK * TOPK];
// RNA-rounded (tf32-clean) copies: lets the GEMM inner loop feed raw f32 bits
// straight into mma.sync.tf32 with NO per-element cvt.
__device__ float g_xr[(size_t)T_TOK * DIM];
__device__ float g_w1r[(size_t)NE * HID * DIM];
__device__ float g_w3r[(size_t)NE * HID * DIM];
__device__ float g_w2r[(size_t)NE * DIM * HID];
__device__ float g_sw1r[(size_t)HID * DIM];
__device__ float g_sw3r[(size_t)HID * DIM];
__device__ float g_sw2r[(size_t)DIM * HID];
// hidden activations: routed slots (T*K) then shared expert (T); stored tf32-clean
__device__ float g_h[(size_t)(T_TOK * TOPK + T_TOK) * HID];

// ---------------- small helpers ----------------------------------------------
__device__ __forceinline__ uint32_t f2tf(float f) {
    uint32_t r;
    asm("cvt.rna.tf32.f32 %0, %1;" : "=r"(r) : "f"(f));
    return r;
}
__device__ __forceinline__ uint32_t smem_u32(const void* p) {
    return (uint32_t)__cvta_generic_to_shared(p);
}
__device__ __forceinline__ void cp16(uint32_t dst, const void* src) {
    asm volatile("cp.async.cg.shared.global [%0], [%1], 16;\n" :: "r"(dst), "l"(src));
}
__device__ __forceinline__ void cp_commit() { asm volatile("cp.async.commit_group;\n"); }
template <int N>
__device__ __forceinline__ void cp_wait() { asm volatile("cp.async.wait_group %0;\n" :: "n"(N)); }

// mma.m16n8k8 tf32, D += A*B
__device__ __forceinline__ void mma_tf32(float* d, const uint32_t* a, const uint32_t* b) {
    asm volatile(
        "mma.sync.aligned.m16n8k8.row.col.f32.tf32.tf32.f32 "
        "{%0,%1,%2,%3},{%4,%5,%6,%7},{%8,%9},{%0,%1,%2,%3};\n"
        : "+f"(d[0]), "+f"(d[1]), "+f"(d[2]), "+f"(d[3])
        : "r"(a[0]), "r"(a[1]), "r"(a[2]), "r"(a[3]), "r"(b[0]), "r"(b[1]));
}

// ---------------- kernel: RNA-round streaming copy ----------------------------
__global__ void round_copy(const float4* __restrict__ src, float4* __restrict__ dst, int n4) {
    for (int i = blockIdx.x * blockDim.x + threadIdx.x; i < n4; i += gridDim.x * blockDim.x) {
        float4 v = src[i];
        v.x = __uint_as_float(f2tf(v.x));
        v.y = __uint_as_float(f2tf(v.y));
        v.z = __uint_as_float(f2tf(v.z));
        v.w = __uint_as_float(f2tf(v.w));
        dst[i] = v;
    }
}

// ---------------- kernel: zero output + counters ------------------------------
__global__ void zero_kernel(float* __restrict__ out) {
    size_t n = (size_t)T_TOK * DIM;
    for (size_t i = (size_t)blockIdx.x * blockDim.x + threadIdx.x; i < n;
         i += (size_t)gridDim.x * blockDim.x)
        out[i] = 0.f;
    if (blockIdx.x == 0 && threadIdx.x < NE) g_counts[threadIdx.x] = 0;
}

// ---------------- kernel: gate (one warp per token) ----------------------------
__global__ void gate_kernel(const float* __restrict__ x, const float* __restrict__ gw) {
    int warp = threadIdx.x >> 5, lane = threadIdx.x & 31;
    int t = blockIdx.x * 8 + warp;
    const float* xr = x + (size_t)t * DIM;
    float acc[NE];
#pragma unroll
    for (int e = 0; e < NE; e++) acc[e] = 0.f;
    for (int k = lane; k < DIM; k += 32) {
        float xv = xr[k];
#pragma unroll
        for (int e = 0; e < NE; e++) acc[e] += xv * gw[e * DIM + k];
    }
#pragma unroll
    for (int e = 0; e < NE; e++)
#pragma unroll
        for (int o = 16; o > 0; o >>= 1) acc[e] += __shfl_xor_sync(0xffffffffu, acc[e], o);
    if (lane == 0) {
        float mx = acc[0];
#pragma unroll
        for (int e = 1; e < NE; e++) mx = fmaxf(mx, acc[e]);
        float p[NE], s = 0.f;
#pragma unroll
        for (int e = 0; e < NE; e++) { p[e] = expf(acc[e] - mx); s += p[e]; }
        float inv = 1.f / s;
#pragma unroll
        for (int e = 0; e < NE; e++) p[e] *= inv;
        int i0 = 0; float b0 = p[0];
#pragma unroll
        for (int e = 1; e < NE; e++) if (p[e] > b0) { b0 = p[e]; i0 = e; }
        int i1 = -1; float b1 = -1.f;
#pragma unroll
        for (int e = 0; e < NE; e++) if (e != i0 && p[e] > b1) { b1 = p[e]; i1 = e; }
        float wn = 1.f / (b0 + b1 + 1e-20f);
        g_topk_idx[2 * t] = i0;     g_topk_idx[2 * t + 1] = i1;
        g_topk_w[2 * t] = b0 * wn;  g_topk_w[2 * t + 1] = b1 * wn;
        atomicAdd(&g_counts[i0], 1);
        atomicAdd(&g_counts[i1], 1);
    }
}

// ---------------- kernel: tiny scan ---------------------------------------------
__global__ void scan_kernel() {
    if (threadIdx.x == 0) {
        int o = 0;
        for (int e = 0; e < NE; e++) { g_offsets[e] = o; o += g_counts[e]; g_fill[e] = 0; }
        g_offsets[NE] = o;
    }
}

// ---------------- kernel: scatter tokens into expert segments --------------------
__global__ void scatter_kernel() {
    int t = blockIdx.x * blockDim.x + threadIdx.x;
    if (t >= T_TOK) return;
#pragma unroll
    for (int k = 0; k < TOPK; k++) {
        int e = g_topk_idx[2 * t + k];
        int pos = g_offsets[e] + atomicAdd(&g_fill[e], 1);
        g_perm[pos] = t;
        g_coef[pos] = g_topk_w[2 * t + k];
    }
}

// ---------------- kernel: FFN1 — h = silu(X W1^T) * (X W3^T) ---------------------
// grid (NT1=22, 64, 9), 256 threads, 111KB smem, warp tile 64x32 (2x4 warp grid)
__global__ __launch_bounds__(256, 1) void ffn1_kernel() {
    extern __shared__ float smem[];
    const int z = blockIdx.z;
    const int rows = (z < NE) ? g_counts[z] : T_TOK;
    const int m0 = blockIdx.y * BM;
    if (m0 >= rows) return;
    const int segoff = (z < NE) ? g_offsets[z] : 0;
    const size_t hbase = (z < NE) ? (size_t)g_offsets[z] : (size_t)(T_TOK * TOPK);
    const float* W1 = (z < NE) ? g_w1r + (size_t)z * HID * DIM : g_sw1r;
    const float* W3 = (z < NE) ? g_w3r + (size_t)z * HID * DIM : g_sw3r;
    const int n0 = blockIdx.x * BN;
    const int tid = threadIdx.x;

    int* stok = (int*)(smem + 2 * ST1_F);
    if (tid < BM) {
        int r = m0 + tid;
        int rr = (r < rows) ? r : m0;
        stok[tid] = (z < NE) ? g_perm[segoff + rr] : rr;
    }
    __syncthreads();

    auto loadA = [&](int it, int buf) {
        float* As = smem + buf * ST1_F;
        const int kt = it * BK;
#pragma unroll
        for (int i = 0; i < 4; i++) {             // 128 rows x 8 chunks / 256 thr
            int j = tid + i * 256;
            int r = j >> 3, c4 = j & 7;
            const float* src = g_xr + (size_t)stok[r] * DIM + kt + c4 * 4;
            cp16(smem_u32(&As[r * SROW + c4 * 4]), src);
        }
    };
    auto loadB = [&](int it, int buf) {
        float* B1 = smem + buf * ST1_F + SA_F;
        float* B3 = B1 + SB_F;
        const int kt = it * BK;
#pragma unroll
        for (int i = 0; i < 4; i++) {             // 128 rows x 8 chunks / 256 thr
            int j = tid + i * 256;
            int n = j >> 3, c4 = j & 7;
            int nn = n0 + n; if (nn >= HID) nn = HID - 1;
            size_t go = (size_t)nn * DIM + kt + c4 * 4;
            cp16(smem_u32(&B1[n * SROW + c4 * 4]), W1 + go);
            cp16(smem_u32(&B3[n * SROW + c4 * 4]), W3 + go);
        }
    };

    const int lane = tid & 31, wid = tid >> 5;
    const int wm = wid & 1, wn = wid >> 1;     // 2x4 warps; warp tile 64x32 (x2 mats)
    const int g = lane >> 2, tg = lane & 3;

    float accG[4][4][4], accU[4][4][4];
#pragma unroll
    for (int a = 0; a < 4; a++)
#pragma unroll
        for (int b = 0; b < 4; b++)
#pragma unroll
            for (int c = 0; c < 4; c++) { accG[a][b][c] = 0.f; accU[a][b][c] = 0.f; }

    loadA(0, 0); loadB(0, 0); cp_commit();
    for (int it = 0; it < NIT1; ++it) {
        const int buf = it & 1;
        if (it + 1 < NIT1) { loadA(it + 1, buf ^ 1); loadB(it + 1, buf ^ 1); cp_commit(); cp_wait<1>(); }
        else               { cp_wait<0>(); }
        __syncthreads();
        const uint32_t* As = (const uint32_t*)(smem + buf * ST1_F);
        const uint32_t* B1 = As + SA_F;
        const uint32_t* B3 = B1 + SB_F;
#pragma unroll
        for (int kk = 0; kk < 4; kk++) {
            const int kb = kk * 8;
            uint32_t af[4][4];
#pragma unroll
            for (int mi = 0; mi < 4; mi++) {
                const int mb = wm * 64 + mi * 16;
                af[mi][0] = As[(mb + g    ) * SROW + kb + tg    ];
                af[mi][1] = As[(mb + g + 8) * SROW + kb + tg    ];
                af[mi][2] = As[(mb + g    ) * SROW + kb + tg + 4];
                af[mi][3] = As[(mb + g + 8) * SROW + kb + tg + 4];
            }
#pragma unroll
            for (int ni = 0; ni < 4; ni++) {
                const int nb = wn * 32 + ni * 8;
                uint32_t b1[2], b3[2];
                b1[0] = B1[(nb + g) * SROW + kb + tg    ];
                b1[1] = B1[(nb + g) * SROW + kb + tg + 4];
                b3[0] = B3[(nb + g) * SROW + kb + tg    ];
                b3[1] = B3[(nb + g) * SROW + kb + tg + 4];
#pragma unroll
                for (int mi = 0; mi < 4; mi++) {
                    mma_tf32(accG[mi][ni], af[mi], b1);
                    mma_tf32(accU[mi][ni], af[mi], b3);
                }
            }
        }
        __syncthreads();
    }

    // epilogue: silu(g)*u -> g_h (pre-rounded so FFN2 needs no cvt)
#pragma unroll
    for (int mi = 0; mi < 4; mi++) {
#pragma unroll
        for (int rh = 0; rh < 2; rh++) {
            const int rr = m0 + wm * 64 + mi * 16 + g + rh * 8;
            if (rr >= rows) continue;
            float* hrow = g_h + (hbase + rr) * (size_t)HID;
#pragma unroll
            for (int ni = 0; ni < 4; ni++) {
                const int c = n0 + wn * 32 + ni * 8 + 2 * tg;
                if (c >= HID) continue;
                float gv0 = accG[mi][ni][rh * 2],     uv0 = accU[mi][ni][rh * 2];
                float gv1 = accG[mi][ni][rh * 2 + 1], uv1 = accU[mi][ni][rh * 2 + 1];
                float2 v;
                v.x = __uint_as_float(f2tf(gv0 / (1.f + expf(-gv0)) * uv0));
                v.y = __uint_as_float(f2tf(gv1 / (1.f + expf(-gv1)) * uv1));
                *(float2*)(hrow + c) = v;
            }
        }
    }
}

// ---------------- kernel: FFN2 — out += coef * (h W2^T) --------------------------
// grid (8, 64, 9), 256 threads, 72KB smem, warp tile 64x32
__global__ __launch_bounds__(256, 2) void ffn2_kernel(float* __restrict__ out) {
    extern __shared__ float smem[];
    const int z = blockIdx.z;
    const int rows = (z < NE) ? g_counts[z] : T_TOK;
    const int m0 = blockIdx.y * BM;
    if (m0 >= rows) return;
    const int segoff = (z < NE) ? g_offsets[z] : 0;
    const size_t hbase = (z < NE) ? (size_t)g_offsets[z] : (size_t)(T_TOK * TOPK);
    const float* W2 = (z < NE) ? g_w2r + (size_t)z * DIM * HID : g_sw2r;
    const int n0 = blockIdx.x * BN;
    const int tid = threadIdx.x;

    auto loadA = [&](int it, int buf) {
        float* As = smem + buf * ST2_F;
        const int kt = it * BK;
#pragma unroll
        for (int i = 0; i < 4; i++) {
            int j = tid + i * 256;
            int r = j >> 3, c4 = j & 7;
            int rr = (m0 + r < rows) ? (m0 + r) : m0;
            const float* src = g_h + (hbase + rr) * (size_t)HID + kt + c4 * 4;
            cp16(smem_u32(&As[r * SROW + c4 * 4]), src);
        }
    };
    auto loadB = [&](int it, int buf) {
        float* Bs = smem + buf * ST2_F + SA_F;
        const int kt = it * BK;
#pragma unroll
        for (int i = 0; i < 4; i++) {
            int j = tid + i * 256;
            int n = j >> 3, c4 = j & 7;
            cp16(smem_u32(&Bs[n * SROW + c4 * 4]),
                 W2 + (size_t)(n0 + n) * HID + kt + c4 * 4);
        }
    };

    const int lane = tid & 31, wid = tid >> 5;
    const int wm = wid & 1, wn = wid >> 1;
    const int g = lane >> 2, tg = lane & 3;

    float acc[4][4][4];
#pragma unroll
    for (int a = 0; a < 4; a++)
#pragma unroll
        for (int b = 0; b < 4; b++)
#pragma unroll
            for (int c = 0; c < 4; c++) acc[a][b][c] = 0.f;

    loadA(0, 0); loadB(0, 0); cp_commit();
    for (int it = 0; it < NIT2; ++it) {
        const int buf = it & 1;
        if (it + 1 < NIT2) { loadA(it + 1, buf ^ 1); loadB(it + 1, buf ^ 1); cp_commit(); cp_wait<1>(); }
        else               { cp_wait<0>(); }
        __syncthreads();
        const uint32_t* As = (const uint32_t*)(smem + buf * ST2_F);
        const uint32_t* Bs = As + SA_F;
#pragma unroll
        for (int kk = 0; kk < 4; kk++) {
            const int kb = kk * 8;
            uint32_t af[4][4];
#pragma unroll
            for (int mi = 0; mi < 4; mi++) {
                const int mb = wm * 64 + mi * 16;
                af[mi][0] = As[(mb + g    ) * SROW + kb + tg    ];
                af[mi][1] = As[(mb + g + 8) * SROW + kb + tg    ];
                af[mi][2] = As[(mb + g    ) * SROW + kb + tg + 4];
                af[mi][3] = As[(mb + g + 8) * SROW + kb + tg + 4];
            }
#pragma unroll
            for (int ni = 0; ni < 4; ni++) {
                const int nb = wn * 32 + ni * 8;
                uint32_t bf[2];
                bf[0] = Bs[(nb + g) * SROW + kb + tg    ];
                bf[1] = Bs[(nb + g) * SROW + kb + tg + 4];
#pragma unroll
                for (int mi = 0; mi < 4; mi++) mma_tf32(acc[mi][ni], af[mi], bf);
            }
        }
        __syncthreads();
    }

    // epilogue: scatter-add with gate coefficient
#pragma unroll
    for (int mi = 0; mi < 4; mi++) {
#pragma unroll
        for (int rh = 0; rh < 2; rh++) {
            const int rr = m0 + wm * 64 + mi * 16 + g + rh * 8;
            if (rr >= rows) continue;
            const int   tok = (z < NE) ? g_perm[segoff + rr] : rr;
            const float cf  = (z < NE) ? g_coef[segoff + rr] : 1.f;
            float* orow = out + (size_t)tok * DIM;
#pragma unroll
            for (int ni = 0; ni < 4; ni++) {
                const int c = n0 + wn * 32 + ni * 8 + 2 * tg;
                atomicAdd(&orow[c],     cf * acc[mi][ni][rh * 2]);
                atomicAdd(&orow[c + 1], cf * acc[mi][ni][rh * 2 + 1]);
            }
        }
    }
}

// ---------------- launcher ---------------------------------------------------------
extern "C" void kernel_launch(void* const* d_in, const int* in_sizes, int n_in,
                              void* d_out, int out_size) {
    const float* x   = (const float*)d_in[0];
    const float* gw  = (const float*)d_in[1];
    const float* w1  = (const float*)d_in[2];
    const float* w2  = (const float*)d_in[3];
    const float* w3  = (const float*)d_in[4];
    const float* sw1 = (const float*)d_in[5];
    const float* sw2 = (const float*)d_in[6];
    const float* sw3 = (const float*)d_in[7];
    float* out = (float*)d_out;

    cudaFuncSetAttribute(ffn1_kernel, cudaFuncAttributeMaxDynamicSharedMemorySize, SMEM1);
    cudaFuncSetAttribute(ffn2_kernel, cudaFuncAttributeMaxDynamicSharedMemorySize, SMEM2);

    float4 *xr, *w1r, *w2r, *w3r, *s1r, *s2r, *s3r;
    cudaGetSymbolAddress((void**)&xr,  g_xr);
    cudaGetSymbolAddress((void**)&w1r, g_w1r);
    cudaGetSymbolAddress((void**)&w2r, g_w2r);
    cudaGetSymbolAddress((void**)&w3r, g_w3r);
    cudaGetSymbolAddress((void**)&s1r, g_sw1r);
    cudaGetSymbolAddress((void**)&s2r, g_sw2r);
    cudaGetSymbolAddress((void**)&s3r, g_sw3r);

    zero_kernel<<<2048, 256>>>(out);

    round_copy<<<2048, 256>>>((const float4*)x,   xr,  (T_TOK * DIM) / 4);
    round_copy<<<4096, 256>>>((const float4*)w1,  w1r, (NE * HID * DIM) / 4);
    round_copy<<<4096, 256>>>((const float4*)w2,  w2r, (NE * DIM * HID) / 4);
    round_copy<<<4096, 256>>>((const float4*)w3,  w3r, (NE * HID * DIM) / 4);
    round_copy<<<1024, 256>>>((const float4*)sw1, s1r, (HID * DIM) / 4);
    round_copy<<<1024, 256>>>((const float4*)sw2, s2r, (DIM * HID) / 4);
    round_copy<<<1024, 256>>>((const float4*)sw3, s3r, (HID * DIM) / 4);

    gate_kernel<<<T_TOK / 8, 256>>>(x, gw);
    scan_kernel<<<1, 32>>>();
    scatter_kernel<<<T_TOK / 256, 256>>>();

    dim3 g1(NT1, T_TOK / BM, NE + 1);
    ffn1_kernel<<<g1, 256, SMEM1>>>();
    dim3 g2(NT2, T_TOK / BM, NE + 1);
    ffn2_kernel<<<g2, 256, SMEM2>>>(out);
}

// round 4
// speedup vs baseline: 1.8156x; 1.8156x over previous
#include <cuda_runtime.h>
#include <cuda_fp16.h>
#include <cstdint>

#define T_TOK 8192
#define DIM   1024
#define HID   2752
#define NE    8
#define TOPK  2

#define BM 128
#define BN 128
#define BK 64                           // k halves per iter (128B per row)
#define SROW 72                         // halves per smem row (conflict-free)
#define SA_H (BM * SROW)                // 9216 halves
#define ST1_H (3 * SA_H)                // A + B1 + B3
#define ST2_H (2 * SA_H)                // A + B
#define SMEM1 (2 * ST1_H * 2 + 512)     // 110592 + 512 B
#define SMEM2 (2 * ST2_H * 2)           // 73728 B

#define NT1 ((HID + BN - 1) / BN)       // 22
#define NT2 (DIM / BN)                  // 8
#define NIT1 (DIM / BK)                 // 16
#define NIT2 (HID / BK)                 // 43

// ---------------- device scratch ------------------------------------------------
__device__ int   g_counts[NE];
__device__ int   g_offsets[NE + 1];
__device__ int   g_fill[NE];
__device__ int   g_topk_idx[T_TOK * TOPK];
__device__ float g_topk_w[T_TOK * TOPK];
__device__ int   g_perm[T_TOK * TOPK];
__device__ float g_coef[T_TOK * TOPK];
// fp16 copies (one-time convert); GEMMs run fp16 HMMA with f32 accumulate
__device__ __half g_xh[(size_t)T_TOK * DIM];
__device__ __half g_w1h[(size_t)NE * HID * DIM];
__device__ __half g_w3h[(size_t)NE * HID * DIM];
__device__ __half g_w2h[(size_t)NE * DIM * HID];
__device__ __half g_sw1h[(size_t)HID * DIM];
__device__ __half g_sw3h[(size_t)HID * DIM];
__device__ __half g_sw2h[(size_t)DIM * HID];
// hidden activations (fp16): routed slots (T*K) then shared expert (T)
__device__ __half g_h[(size_t)(T_TOK * TOPK + T_TOK) * HID];

// ---------------- helpers --------------------------------------------------------
__device__ __forceinline__ uint32_t smem_u32(const void* p) {
    return (uint32_t)__cvta_generic_to_shared(p);
}
__device__ __forceinline__ void cp16(uint32_t dst, const void* src) {
    asm volatile("cp.async.cg.shared.global [%0], [%1], 16;\n" :: "r"(dst), "l"(src));
}
__device__ __forceinline__ void cp_commit() { asm volatile("cp.async.commit_group;\n"); }
template <int N>
__device__ __forceinline__ void cp_wait() { asm volatile("cp.async.wait_group %0;\n" :: "n"(N)); }

// mma m16n8k16 fp16 in, f32 acc: D += A*B
__device__ __forceinline__ void mma_f16(float* d, const uint32_t* a, const uint32_t* b) {
    asm volatile(
        "mma.sync.aligned.m16n8k16.row.col.f32.f16.f16.f32 "
        "{%0,%1,%2,%3},{%4,%5,%6,%7},{%8,%9},{%0,%1,%2,%3};\n"
        : "+f"(d[0]), "+f"(d[1]), "+f"(d[2]), "+f"(d[3])
        : "r"(a[0]), "r"(a[1]), "r"(a[2]), "r"(a[3]), "r"(b[0]), "r"(b[1]));
}

// ---------------- kernel: fused f32 -> f16 convert (all tensors) ------------------
struct CvtArgs {
    const float4* src[7];
    uint2*        dst[7];
    int           n4[7];
};
__global__ void cvt_all_kernel(CvtArgs a) {
    const int stride = gridDim.x * blockDim.x;
    const int t0 = blockIdx.x * blockDim.x + threadIdx.x;
#pragma unroll
    for (int s = 0; s < 7; s++) {
        const float4* __restrict__ src = a.src[s];
        uint2* __restrict__ dst = a.dst[s];
        const int n = a.n4[s];
        for (int i = t0; i < n; i += stride) {
            float4 v = src[i];
            __half2 lo = __floats2half2_rn(v.x, v.y);
            __half2 hi = __floats2half2_rn(v.z, v.w);
            uint2 o;
            o.x = *(uint32_t*)&lo;
            o.y = *(uint32_t*)&hi;
            dst[i] = o;
        }
    }
}

// ---------------- kernel: zero output + counters ----------------------------------
__global__ void zero_kernel(float* __restrict__ out) {
    size_t n = (size_t)T_TOK * DIM;
    for (size_t i = (size_t)blockIdx.x * blockDim.x + threadIdx.x; i < n;
         i += (size_t)gridDim.x * blockDim.x)
        out[i] = 0.f;
    if (blockIdx.x == 0 && threadIdx.x < NE) g_counts[threadIdx.x] = 0;
}

// ---------------- kernel: gate (one warp per token, raw f32 x) ---------------------
__global__ void gate_kernel(const float* __restrict__ x, const float* __restrict__ gw) {
    int warp = threadIdx.x >> 5, lane = threadIdx.x & 31;
    int t = blockIdx.x * 8 + warp;
    const float* xr = x + (size_t)t * DIM;
    float acc[NE];
#pragma unroll
    for (int e = 0; e < NE; e++) acc[e] = 0.f;
    for (int k = lane; k < DIM; k += 32) {
        float xv = xr[k];
#pragma unroll
        for (int e = 0; e < NE; e++) acc[e] += xv * gw[e * DIM + k];
    }
#pragma unroll
    for (int e = 0; e < NE; e++)
#pragma unroll
        for (int o = 16; o > 0; o >>= 1) acc[e] += __shfl_xor_sync(0xffffffffu, acc[e], o);
    if (lane == 0) {
        float mx = acc[0];
#pragma unroll
        for (int e = 1; e < NE; e++) mx = fmaxf(mx, acc[e]);
        float p[NE], s = 0.f;
#pragma unroll
        for (int e = 0; e < NE; e++) { p[e] = expf(acc[e] - mx); s += p[e]; }
        float inv = 1.f / s;
#pragma unroll
        for (int e = 0; e < NE; e++) p[e] *= inv;
        int i0 = 0; float b0 = p[0];
#pragma unroll
        for (int e = 1; e < NE; e++) if (p[e] > b0) { b0 = p[e]; i0 = e; }
        int i1 = -1; float b1 = -1.f;
#pragma unroll
        for (int e = 0; e < NE; e++) if (e != i0 && p[e] > b1) { b1 = p[e]; i1 = e; }
        float wn = 1.f / (b0 + b1 + 1e-20f);
        g_topk_idx[2 * t] = i0;     g_topk_idx[2 * t + 1] = i1;
        g_topk_w[2 * t] = b0 * wn;  g_topk_w[2 * t + 1] = b1 * wn;
        atomicAdd(&g_counts[i0], 1);
        atomicAdd(&g_counts[i1], 1);
    }
}

// ---------------- kernel: tiny scan -------------------------------------------------
__global__ void scan_kernel() {
    if (threadIdx.x == 0) {
        int o = 0;
        for (int e = 0; e < NE; e++) { g_offsets[e] = o; o += g_counts[e]; g_fill[e] = 0; }
        g_offsets[NE] = o;
    }
}

// ---------------- kernel: scatter tokens into expert segments ------------------------
__global__ void scatter_kernel() {
    int t = blockIdx.x * blockDim.x + threadIdx.x;
    if (t >= T_TOK) return;
#pragma unroll
    for (int k = 0; k < TOPK; k++) {
        int e = g_topk_idx[2 * t + k];
        int pos = g_offsets[e] + atomicAdd(&g_fill[e], 1);
        g_perm[pos] = t;
        g_coef[pos] = g_topk_w[2 * t + k];
    }
}

// ---------------- kernel: FFN1 — h = silu(X W1^T) * (X W3^T), fp16 HMMA --------------
// grid (22, 64, 9), 256 threads, warp tile 64x32 over two output matrices
__global__ __launch_bounds__(256, 1) void ffn1_kernel() {
    extern __shared__ __half smem[];
    const int z = blockIdx.z;
    const int rows = (z < NE) ? g_counts[z] : T_TOK;
    const int m0 = blockIdx.y * BM;
    if (m0 >= rows) return;
    const int segoff = (z < NE) ? g_offsets[z] : 0;
    const size_t hbase = (z < NE) ? (size_t)g_offsets[z] : (size_t)(T_TOK * TOPK);
    const __half* W1 = (z < NE) ? g_w1h + (size_t)z * HID * DIM : g_sw1h;
    const __half* W3 = (z < NE) ? g_w3h + (size_t)z * HID * DIM : g_sw3h;
    const int n0 = blockIdx.x * BN;
    const int tid = threadIdx.x;

    int* stok = (int*)(smem + 2 * ST1_H);
    if (tid < BM) {
        int r = m0 + tid;
        int rr = (r < rows) ? r : m0;
        stok[tid] = (z < NE) ? g_perm[segoff + rr] : rr;
    }
    __syncthreads();

    auto loadA = [&](int it, int buf) {
        __half* As = smem + buf * ST1_H;
        const int kt = it * BK;
#pragma unroll
        for (int i = 0; i < 4; i++) {             // 128 rows x 8 chunks(16B) / 256 thr
            int j = tid + i * 256;
            int r = j >> 3, c8 = j & 7;
            const __half* src = g_xh + (size_t)stok[r] * DIM + kt + c8 * 8;
            cp16(smem_u32(&As[r * SROW + c8 * 8]), src);
        }
    };
    auto loadB = [&](int it, int buf) {
        __half* B1 = smem + buf * ST1_H + SA_H;
        __half* B3 = B1 + SA_H;
        const int kt = it * BK;
#pragma unroll
        for (int i = 0; i < 4; i++) {
            int j = tid + i * 256;
            int n = j >> 3, c8 = j & 7;
            int nn = n0 + n; if (nn >= HID) nn = HID - 1;
            size_t go = (size_t)nn * DIM + kt + c8 * 8;
            cp16(smem_u32(&B1[n * SROW + c8 * 8]), W1 + go);
            cp16(smem_u32(&B3[n * SROW + c8 * 8]), W3 + go);
        }
    };

    const int lane = tid & 31, wid = tid >> 5;
    const int wm = wid & 1, wn = wid >> 1;       // 2x4 warps; warp tile 64x32
    const int g = lane >> 2, tg = lane & 3;

    float accG[4][4][4], accU[4][4][4];
#pragma unroll
    for (int a = 0; a < 4; a++)
#pragma unroll
        for (int b = 0; b < 4; b++)
#pragma unroll
            for (int c = 0; c < 4; c++) { accG[a][b][c] = 0.f; accU[a][b][c] = 0.f; }

    loadA(0, 0); loadB(0, 0); cp_commit();
    for (int it = 0; it < NIT1; ++it) {
        const int buf = it & 1;
        if (it + 1 < NIT1) { loadA(it + 1, buf ^ 1); loadB(it + 1, buf ^ 1); cp_commit(); cp_wait<1>(); }
        else               { cp_wait<0>(); }
        __syncthreads();
        const __half* As = smem + buf * ST1_H;
        const __half* B1 = As + SA_H;
        const __half* B3 = B1 + SA_H;
#pragma unroll
        for (int kk = 0; kk < 4; kk++) {           // 4 x k16
            const int kb = kk * 16;
            uint32_t af[4][4];
#pragma unroll
            for (int mi = 0; mi < 4; mi++) {
                const int mb = wm * 64 + mi * 16;
                af[mi][0] = *(const uint32_t*)&As[(mb + g    ) * SROW + kb + 2 * tg    ];
                af[mi][1] = *(const uint32_t*)&As[(mb + g + 8) * SROW + kb + 2 * tg    ];
                af[mi][2] = *(const uint32_t*)&As[(mb + g    ) * SROW + kb + 2 * tg + 8];
                af[mi][3] = *(const uint32_t*)&As[(mb + g + 8) * SROW + kb + 2 * tg + 8];
            }
#pragma unroll
            for (int ni = 0; ni < 4; ni++) {
                const int nb = wn * 32 + ni * 8;
                uint32_t b1[2], b3[2];
                b1[0] = *(const uint32_t*)&B1[(nb + g) * SROW + kb + 2 * tg    ];
                b1[1] = *(const uint32_t*)&B1[(nb + g) * SROW + kb + 2 * tg + 8];
                b3[0] = *(const uint32_t*)&B3[(nb + g) * SROW + kb + 2 * tg    ];
                b3[1] = *(const uint32_t*)&B3[(nb + g) * SROW + kb + 2 * tg + 8];
#pragma unroll
                for (int mi = 0; mi < 4; mi++) {
                    mma_f16(accG[mi][ni], af[mi], b1);
                    mma_f16(accU[mi][ni], af[mi], b3);
                }
            }
        }
        __syncthreads();
    }

    // epilogue: silu(g)*u -> g_h (fp16)
#pragma unroll
    for (int mi = 0; mi < 4; mi++) {
#pragma unroll
        for (int rh = 0; rh < 2; rh++) {
            const int rr = m0 + wm * 64 + mi * 16 + g + rh * 8;
            if (rr >= rows) continue;
            __half* hrow = g_h + (hbase + rr) * (size_t)HID;
#pragma unroll
            for (int ni = 0; ni < 4; ni++) {
                const int c = n0 + wn * 32 + ni * 8 + 2 * tg;
                if (c >= HID) continue;
                float gv0 = accG[mi][ni][rh * 2],     uv0 = accU[mi][ni][rh * 2];
                float gv1 = accG[mi][ni][rh * 2 + 1], uv1 = accU[mi][ni][rh * 2 + 1];
                float h0 = gv0 / (1.f + expf(-gv0)) * uv0;
                float h1 = gv1 / (1.f + expf(-gv1)) * uv1;
                __half2 hv = __floats2half2_rn(h0, h1);
                *(uint32_t*)(hrow + c) = *(uint32_t*)&hv;
            }
        }
    }
}

// ---------------- kernel: FFN2 — out += coef * (h W2^T), fp16 HMMA --------------------
// grid (8, 64, 9), 256 threads
__global__ __launch_bounds__(256, 2) void ffn2_kernel(float* __restrict__ out) {
    extern __shared__ __half smem[];
    const int z = blockIdx.z;
    const int rows = (z < NE) ? g_counts[z] : T_TOK;
    const int m0 = blockIdx.y * BM;
    if (m0 >= rows) return;
    const int segoff = (z < NE) ? g_offsets[z] : 0;
    const size_t hbase = (z < NE) ? (size_t)g_offsets[z] : (size_t)(T_TOK * TOPK);
    const __half* W2 = (z < NE) ? g_w2h + (size_t)z * DIM * HID : g_sw2h;
    const int n0 = blockIdx.x * BN;
    const int tid = threadIdx.x;

    auto loadA = [&](int it, int buf) {
        __half* As = smem + buf * ST2_H;
        const int kt = it * BK;
#pragma unroll
        for (int i = 0; i < 4; i++) {
            int j = tid + i * 256;
            int r = j >> 3, c8 = j & 7;
            int rr = (m0 + r < rows) ? (m0 + r) : m0;
            const __half* src = g_h + (hbase + rr) * (size_t)HID + kt + c8 * 8;
            cp16(smem_u32(&As[r * SROW + c8 * 8]), src);
        }
    };
    auto loadB = [&](int it, int buf) {
        __half* Bs = smem + buf * ST2_H + SA_H;
        const int kt = it * BK;
#pragma unroll
        for (int i = 0; i < 4; i++) {
            int j = tid + i * 256;
            int n = j >> 3, c8 = j & 7;
            cp16(smem_u32(&Bs[n * SROW + c8 * 8]),
                 W2 + (size_t)(n0 + n) * HID + kt + c8 * 8);
        }
    };

    const int lane = tid & 31, wid = tid >> 5;
    const int wm = wid & 1, wn = wid >> 1;
    const int g = lane >> 2, tg = lane & 3;

    float acc[4][4][4];
#pragma unroll
    for (int a = 0; a < 4; a++)
#pragma unroll
        for (int b = 0; b < 4; b++)
#pragma unroll
            for (int c = 0; c < 4; c++) acc[a][b][c] = 0.f;

    loadA(0, 0); loadB(0, 0); cp_commit();
    for (int it = 0; it < NIT2; ++it) {
        const int buf = it & 1;
        if (it + 1 < NIT2) { loadA(it + 1, buf ^ 1); loadB(it + 1, buf ^ 1); cp_commit(); cp_wait<1>(); }
        else               { cp_wait<0>(); }
        __syncthreads();
        const __half* As = smem + buf * ST2_H;
        const __half* Bs = As + SA_H;
#pragma unroll
        for (int kk = 0; kk < 4; kk++) {
            const int kb = kk * 16;
            uint32_t af[4][4];
#pragma unroll
            for (int mi = 0; mi < 4; mi++) {
                const int mb = wm * 64 + mi * 16;
                af[mi][0] = *(const uint32_t*)&As[(mb + g    ) * SROW + kb + 2 * tg    ];
                af[mi][1] = *(const uint32_t*)&As[(mb + g + 8) * SROW + kb + 2 * tg    ];
                af[mi][2] = *(const uint32_t*)&As[(mb + g    ) * SROW + kb + 2 * tg + 8];
                af[mi][3] = *(const uint32_t*)&As[(mb + g + 8) * SROW + kb + 2 * tg + 8];
            }
#pragma unroll
            for (int ni = 0; ni < 4; ni++) {
                const int nb = wn * 32 + ni * 8;
                uint32_t bf[2];
                bf[0] = *(const uint32_t*)&Bs[(nb + g) * SROW + kb + 2 * tg    ];
                bf[1] = *(const uint32_t*)&Bs[(nb + g) * SROW + kb + 2 * tg + 8];
#pragma unroll
                for (int mi = 0; mi < 4; mi++) mma_f16(acc[mi][ni], af[mi], bf);
            }
        }
        __syncthreads();
    }

    // epilogue: scatter-add with gate coefficient
#pragma unroll
    for (int mi = 0; mi < 4; mi++) {
#pragma unroll
        for (int rh = 0; rh < 2; rh++) {
            const int rr = m0 + wm * 64 + mi * 16 + g + rh * 8;
            if (rr >= rows) continue;
            const int   tok = (z < NE) ? g_perm[segoff + rr] : rr;
            const float cf  = (z < NE) ? g_coef[segoff + rr] : 1.f;
            float* orow = out + (size_t)tok * DIM;
#pragma unroll
            for (int ni = 0; ni < 4; ni++) {
                const int c = n0 + wn * 32 + ni * 8 + 2 * tg;
                atomicAdd(&orow[c],     cf * acc[mi][ni][rh * 2]);
                atomicAdd(&orow[c + 1], cf * acc[mi][ni][rh * 2 + 1]);
            }
        }
    }
}

// ---------------- launcher --------------------------------------------------------------
extern "C" void kernel_launch(void* const* d_in, const int* in_sizes, int n_in,
                              void* d_out, int out_size) {
    const float* x   = (const float*)d_in[0];
    const float* gw  = (const float*)d_in[1];
    const float* w1  = (const float*)d_in[2];
    const float* w2  = (const float*)d_in[3];
    const float* w3  = (const float*)d_in[4];
    const float* sw1 = (const float*)d_in[5];
    const float* sw2 = (const float*)d_in[6];
    const float* sw3 = (const float*)d_in[7];
    float* out = (float*)d_out;

    cudaFuncSetAttribute(ffn1_kernel, cudaFuncAttributeMaxDynamicSharedMemorySize, SMEM1);
    cudaFuncSetAttribute(ffn2_kernel, cudaFuncAttributeMaxDynamicSharedMemorySize, SMEM2);

    CvtArgs ca;
    void* p;
    cudaGetSymbolAddress(&p, g_xh);   ca.dst[0] = (uint2*)p; ca.src[0] = (const float4*)x;   ca.n4[0] = (T_TOK * DIM) / 4;
    cudaGetSymbolAddress(&p, g_w1h);  ca.dst[1] = (uint2*)p; ca.src[1] = (const float4*)w1;  ca.n4[1] = (NE * HID * DIM) / 4;
    cudaGetSymbolAddress(&p, g_w2h);  ca.dst[2] = (uint2*)p; ca.src[2] = (const float4*)w2;  ca.n4[2] = (NE * DIM * HID) / 4;
    cudaGetSymbolAddress(&p, g_w3h);  ca.dst[3] = (uint2*)p; ca.src[3] = (const float4*)w3;  ca.n4[3] = (NE * HID * DIM) / 4;
    cudaGetSymbolAddress(&p, g_sw1h); ca.dst[4] = (uint2*)p; ca.src[4] = (const float4*)sw1; ca.n4[4] = (HID * DIM) / 4;
    cudaGetSymbolAddress(&p, g_sw2h); ca.dst[5] = (uint2*)p; ca.src[5] = (const float4*)sw2; ca.n4[5] = (DIM * HID) / 4;
    cudaGetSymbolAddress(&p, g_sw3h); ca.dst[6] = (uint2*)p; ca.src[6] = (const float4*)sw3; ca.n4[6] = (HID * DIM) / 4;

    // launch order arranged so ffn1 is the 6th launch (ncu -s 5 -c 1 captures it)
    zero_kernel<<<2048, 256>>>(out);                 // 1
    cvt_all_kernel<<<4096, 256>>>(ca);               // 2
    gate_kernel<<<T_TOK / 8, 256>>>(x, gw);          // 3
    scan_kernel<<<1, 32>>>();                        // 4
    scatter_kernel<<<T_TOK / 256, 256>>>();          // 5

    dim3 g1(NT1, T_TOK / BM, NE + 1);
    ffn1_kernel<<<g1, 256, SMEM1>>>();               // 6  <-- profiled
    dim3 g2(NT2, T_TOK / BM, NE + 1);
    ffn2_kernel<<<g2, 256, SMEM2>>>(out);            // 7
}

// round 5
// speedup vs baseline: 2.1186x; 1.1669x over previous
#include <cuda_runtime.h>
#include <cuda_fp16.h>
#include <cstdint>

#define T_TOK 8192
#define DIM   1024
#define HID   2752
#define NE    8
#define TOPK  2

#define BM 128
#define BN 128
#define BK 64                            // halves per k-iter (128B rows)
#define TILE_B (BM * 128)                // 16384 B per matrix tile
#define ST1 (3 * TILE_B)                 // ffn1 stage: A + B1 + B3 = 49152 B
#define ST2 (2 * TILE_B)                 // ffn2 stage: A + B = 32768 B
#define SMEM1 (3 * ST1 + 512)            // 3-stage + token list = 147968 B
#define SMEM2 (3 * ST2)                  // 98304 B

#define NT1 ((HID + BN - 1) / BN)        // 22
#define NT2 (DIM / BN)                   // 8
#define NIT1 (DIM / BK)                  // 16
#define NIT2 (HID / BK)                  // 43

// swizzled byte offset within one 128-row x 128B tile: row r, 16B chunk c (0..7)
#define SWZ(r, c) ((r) * 128 + ((((c) ^ ((r) & 7))) * 16))

// ---------------- device scratch ------------------------------------------------
__device__ int   g_counts[NE];
__device__ int   g_offsets[NE + 1];
__device__ int   g_fill[NE];
__device__ int   g_topk_idx[T_TOK * TOPK];
__device__ float g_topk_w[T_TOK * TOPK];
__device__ int   g_perm[T_TOK * TOPK];
__device__ float g_coef[T_TOK * TOPK];
__device__ __half g_xh[(size_t)T_TOK * DIM];
__device__ __half g_w1h[(size_t)NE * HID * DIM];
__device__ __half g_w3h[(size_t)NE * HID * DIM];
__device__ __half g_w2h[(size_t)NE * DIM * HID];
__device__ __half g_sw1h[(size_t)HID * DIM];
__device__ __half g_sw3h[(size_t)HID * DIM];
__device__ __half g_sw2h[(size_t)DIM * HID];
__device__ __half g_h[(size_t)(T_TOK * TOPK + T_TOK) * HID];

// ---------------- helpers --------------------------------------------------------
__device__ __forceinline__ uint32_t smem_u32(const void* p) {
    return (uint32_t)__cvta_generic_to_shared(p);
}
__device__ __forceinline__ void cp16(uint32_t dst, const void* src) {
    asm volatile("cp.async.cg.shared.global [%0], [%1], 16;\n" :: "r"(dst), "l"(src));
}
__device__ __forceinline__ void cp_commit() { asm volatile("cp.async.commit_group;\n"); }
template <int N>
__device__ __forceinline__ void cp_wait() { asm volatile("cp.async.wait_group %0;\n" :: "n"(N)); }

__device__ __forceinline__ void ldm_x4(uint32_t* r, uint32_t addr) {
    asm volatile("ldmatrix.sync.aligned.m8n8.x4.shared.b16 {%0,%1,%2,%3}, [%4];"
                 : "=r"(r[0]), "=r"(r[1]), "=r"(r[2]), "=r"(r[3]) : "r"(addr));
}
__device__ __forceinline__ void ldm_x2(uint32_t* r, uint32_t addr) {
    asm volatile("ldmatrix.sync.aligned.m8n8.x2.shared.b16 {%0,%1}, [%2];"
                 : "=r"(r[0]), "=r"(r[1]) : "r"(addr));
}

// mma m16n8k16 fp16 in, f32 acc: D += A*B
__device__ __forceinline__ void mma_f16(float* d, const uint32_t* a, const uint32_t* b) {
    asm volatile(
        "mma.sync.aligned.m16n8k16.row.col.f32.f16.f16.f32 "
        "{%0,%1,%2,%3},{%4,%5,%6,%7},{%8,%9},{%0,%1,%2,%3};\n"
        : "+f"(d[0]), "+f"(d[1]), "+f"(d[2]), "+f"(d[3])
        : "r"(a[0]), "r"(a[1]), "r"(a[2]), "r"(a[3]), "r"(b[0]), "r"(b[1]));
}

// ---------------- kernel: fused f32 -> f16 convert --------------------------------
struct CvtArgs {
    const float4* src[7];
    uint2*        dst[7];
    int           n4[7];
};
__global__ void cvt_all_kernel(CvtArgs a) {
    const int stride = gridDim.x * blockDim.x;
    const int t0 = blockIdx.x * blockDim.x + threadIdx.x;
#pragma unroll
    for (int s = 0; s < 7; s++) {
        const float4* __restrict__ src = a.src[s];
        uint2* __restrict__ dst = a.dst[s];
        const int n = a.n4[s];
        for (int i = t0; i < n; i += stride) {
            float4 v = src[i];
            __half2 lo = __floats2half2_rn(v.x, v.y);
            __half2 hi = __floats2half2_rn(v.z, v.w);
            uint2 o;
            o.x = *(uint32_t*)&lo;
            o.y = *(uint32_t*)&hi;
            dst[i] = o;
        }
    }
}

// ---------------- kernel: zero output + counters ----------------------------------
__global__ void zero_kernel(float* __restrict__ out) {
    size_t n = (size_t)T_TOK * DIM;
    for (size_t i = (size_t)blockIdx.x * blockDim.x + threadIdx.x; i < n;
         i += (size_t)gridDim.x * blockDim.x)
        out[i] = 0.f;
    if (blockIdx.x == 0 && threadIdx.x < NE) g_counts[threadIdx.x] = 0;
}

// ---------------- kernel: gate --------------------------------------------------------
__global__ void gate_kernel(const float* __restrict__ x, const float* __restrict__ gw) {
    int warp = threadIdx.x >> 5, lane = threadIdx.x & 31;
    int t = blockIdx.x * 8 + warp;
    const float* xr = x + (size_t)t * DIM;
    float acc[NE];
#pragma unroll
    for (int e = 0; e < NE; e++) acc[e] = 0.f;
    for (int k = lane; k < DIM; k += 32) {
        float xv = xr[k];
#pragma unroll
        for (int e = 0; e < NE; e++) acc[e] += xv * gw[e * DIM + k];
    }
#pragma unroll
    for (int e = 0; e < NE; e++)
#pragma unroll
        for (int o = 16; o > 0; o >>= 1) acc[e] += __shfl_xor_sync(0xffffffffu, acc[e], o);
    if (lane == 0) {
        float mx = acc[0];
#pragma unroll
        for (int e = 1; e < NE; e++) mx = fmaxf(mx, acc[e]);
        float p[NE], s = 0.f;
#pragma unroll
        for (int e = 0; e < NE; e++) { p[e] = expf(acc[e] - mx); s += p[e]; }
        float inv = 1.f / s;
#pragma unroll
        for (int e = 0; e < NE; e++) p[e] *= inv;
        int i0 = 0; float b0 = p[0];
#pragma unroll
        for (int e = 1; e < NE; e++) if (p[e] > b0) { b0 = p[e]; i0 = e; }
        int i1 = -1; float b1 = -1.f;
#pragma unroll
        for (int e = 0; e < NE; e++) if (e != i0 && p[e] > b1) { b1 = p[e]; i1 = e; }
        float wn = 1.f / (b0 + b1 + 1e-20f);
        g_topk_idx[2 * t] = i0;     g_topk_idx[2 * t + 1] = i1;
        g_topk_w[2 * t] = b0 * wn;  g_topk_w[2 * t + 1] = b1 * wn;
        atomicAdd(&g_counts[i0], 1);
        atomicAdd(&g_counts[i1], 1);
    }
}

// ---------------- kernel: tiny scan -----------------------------------------------------
__global__ void scan_kernel() {
    if (threadIdx.x == 0) {
        int o = 0;
        for (int e = 0; e < NE; e++) { g_offsets[e] = o; o += g_counts[e]; g_fill[e] = 0; }
        g_offsets[NE] = o;
    }
}

// ---------------- kernel: scatter --------------------------------------------------------
__global__ void scatter_kernel() {
    int t = blockIdx.x * blockDim.x + threadIdx.x;
    if (t >= T_TOK) return;
#pragma unroll
    for (int k = 0; k < TOPK; k++) {
        int e = g_topk_idx[2 * t + k];
        int pos = g_offsets[e] + atomicAdd(&g_fill[e], 1);
        g_perm[pos] = t;
        g_coef[pos] = g_topk_w[2 * t + k];
    }
}

// ---------------- kernel: FFN1 — h = silu(X W1^T) * (X W3^T) ------------------------------
__global__ __launch_bounds__(256, 1) void ffn1_kernel() {
    extern __shared__ char smem[];
    const uint32_t sbase = smem_u32(smem);
    const int z = blockIdx.z;
    const int rows = (z < NE) ? g_counts[z] : T_TOK;
    const int m0 = blockIdx.y * BM;
    if (m0 >= rows) return;
    const int segoff = (z < NE) ? g_offsets[z] : 0;
    const size_t hbase = (z < NE) ? (size_t)g_offsets[z] : (size_t)(T_TOK * TOPK);
    const __half* W1 = (z < NE) ? g_w1h + (size_t)z * HID * DIM : g_sw1h;
    const __half* W3 = (z < NE) ? g_w3h + (size_t)z * HID * DIM : g_sw3h;
    const int n0 = blockIdx.x * BN;
    const int tid = threadIdx.x;

    int* stok = (int*)(smem + 3 * ST1);
    if (tid < BM) {
        int r = m0 + tid;
        int rr = (r < rows) ? r : m0;
        stok[tid] = (z < NE) ? g_perm[segoff + rr] : rr;
    }
    __syncthreads();

    auto loadAll = [&](int it, int stg) {
        const uint32_t base = sbase + stg * ST1;
        const int kt = it * BK;
#pragma unroll
        for (int i = 0; i < 4; i++) {
            int j = tid + i * 256;
            int r = j >> 3, c8 = j & 7;
            uint32_t sw = SWZ(r, c8);
            cp16(base + sw, g_xh + (size_t)stok[r] * DIM + kt + c8 * 8);
            int nn = n0 + r; if (nn >= HID) nn = HID - 1;
            size_t go = (size_t)nn * DIM + kt + c8 * 8;
            cp16(base + TILE_B + sw,     W1 + go);
            cp16(base + 2 * TILE_B + sw, W3 + go);
        }
    };

    const int lane = tid & 31, wid = tid >> 5;
    const int wm = wid & 1, wn = wid >> 1;        // warp tile 64x32 (x2 matrices)
    const int g = lane >> 2, tg = lane & 3;

    // per-lane ldmatrix address invariants
    const uint32_t a_row = (uint32_t)(wm * 64 + (lane & 15));
    const uint32_t a_roff = a_row * 128;
    const uint32_t a_x = lane & 7, a_c = (uint32_t)(lane >> 4);
    const uint32_t b_row = (uint32_t)(wn * 32 + (lane & 7));
    const uint32_t b_roff = b_row * 128;
    const uint32_t b_c = (uint32_t)((lane >> 3) & 1);

    float accG[4][4][4], accU[4][4][4];
#pragma unroll
    for (int a = 0; a < 4; a++)
#pragma unroll
        for (int b = 0; b < 4; b++)
#pragma unroll
            for (int c = 0; c < 4; c++) { accG[a][b][c] = 0.f; accU[a][b][c] = 0.f; }

    loadAll(0, 0); cp_commit();
    loadAll(1, 1); cp_commit();
    for (int it = 0; it < NIT1; ++it) {
        const int stg = it % 3;
        if (it + 1 < NIT1) cp_wait<1>(); else cp_wait<0>();
        __syncthreads();
        if (it + 2 < NIT1) { loadAll(it + 2, (it + 2) % 3); cp_commit(); }
        const uint32_t aB = sbase + stg * ST1;
        const uint32_t b1B = aB + TILE_B;
        const uint32_t b3B = aB + 2 * TILE_B;
#pragma unroll
        for (int kk = 0; kk < 4; kk++) {
            const uint32_t ach = ((kk * 2 + a_c) ^ a_x) * 16;
            const uint32_t bch = ((kk * 2 + b_c) ^ a_x) * 16;
            uint32_t af[4][4];
#pragma unroll
            for (int mi = 0; mi < 4; mi++)
                ldm_x4(af[mi], aB + a_roff + mi * 2048 + ach);
#pragma unroll
            for (int ni = 0; ni < 4; ni++) {
                uint32_t b1[2], b3[2];
                ldm_x2(b1, b1B + b_roff + ni * 1024 + bch);
                ldm_x2(b3, b3B + b_roff + ni * 1024 + bch);
#pragma unroll
                for (int mi = 0; mi < 4; mi++) {
                    mma_f16(accG[mi][ni], af[mi], b1);
                    mma_f16(accU[mi][ni], af[mi], b3);
                }
            }
        }
    }

    // epilogue: silu(g)*u -> g_h (fp16)
#pragma unroll
    for (int mi = 0; mi < 4; mi++) {
#pragma unroll
        for (int rh = 0; rh < 2; rh++) {
            const int rr = m0 + wm * 64 + mi * 16 + g + rh * 8;
            if (rr >= rows) continue;
            __half* hrow = g_h + (hbase + rr) * (size_t)HID;
#pragma unroll
            for (int ni = 0; ni < 4; ni++) {
                const int c = n0 + wn * 32 + ni * 8 + 2 * tg;
                if (c >= HID) continue;
                float gv0 = accG[mi][ni][rh * 2],     uv0 = accU[mi][ni][rh * 2];
                float gv1 = accG[mi][ni][rh * 2 + 1], uv1 = accU[mi][ni][rh * 2 + 1];
                float h0 = gv0 / (1.f + expf(-gv0)) * uv0;
                float h1 = gv1 / (1.f + expf(-gv1)) * uv1;
                __half2 hv = __floats2half2_rn(h0, h1);
                *(uint32_t*)(hrow + c) = *(uint32_t*)&hv;
            }
        }
    }
}

// ---------------- kernel: FFN2 — out += coef * (h W2^T) -------------------------------------
__global__ __launch_bounds__(256, 2) void ffn2_kernel(float* __restrict__ out) {
    extern __shared__ char smem[];
    const uint32_t sbase = smem_u32(smem);
    const int z = blockIdx.z;
    const int rows = (z < NE) ? g_counts[z] : T_TOK;
    const int m0 = blockIdx.y * BM;
    if (m0 >= rows) return;
    const int segoff = (z < NE) ? g_offsets[z] : 0;
    const size_t hbase = (z < NE) ? (size_t)g_offsets[z] : (size_t)(T_TOK * TOPK);
    const __half* W2 = (z < NE) ? g_w2h + (size_t)z * DIM * HID : g_sw2h;
    const int n0 = blockIdx.x * BN;
    const int tid = threadIdx.x;

    auto loadAll = [&](int it, int stg) {
        const uint32_t base = sbase + stg * ST2;
        const int kt = it * BK;
#pragma unroll
        for (int i = 0; i < 4; i++) {
            int j = tid + i * 256;
            int r = j >> 3, c8 = j & 7;
            uint32_t sw = SWZ(r, c8);
            int rr = (m0 + r < rows) ? (m0 + r) : m0;
            cp16(base + sw, g_h + (hbase + rr) * (size_t)HID + kt + c8 * 8);
            cp16(base + TILE_B + sw, W2 + (size_t)(n0 + r) * HID + kt + c8 * 8);
        }
    };

    const int lane = tid & 31, wid = tid >> 5;
    const int wm = wid & 1, wn = wid >> 1;
    const int g = lane >> 2, tg = lane & 3;

    const uint32_t a_row = (uint32_t)(wm * 64 + (lane & 15));
    const uint32_t a_roff = a_row * 128;
    const uint32_t a_x = lane & 7, a_c = (uint32_t)(lane >> 4);
    const uint32_t b_row = (uint32_t)(wn * 32 + (lane & 7));
    const uint32_t b_roff = b_row * 128;
    const uint32_t b_c = (uint32_t)((lane >> 3) & 1);

    float acc[4][4][4];
#pragma unroll
    for (int a = 0; a < 4; a++)
#pragma unroll
        for (int b = 0; b < 4; b++)
#pragma unroll
            for (int c = 0; c < 4; c++) acc[a][b][c] = 0.f;

    loadAll(0, 0); cp_commit();
    loadAll(1, 1); cp_commit();
    for (int it = 0; it < NIT2; ++it) {
        const int stg = it % 3;
        if (it + 1 < NIT2) cp_wait<1>(); else cp_wait<0>();
        __syncthreads();
        if (it + 2 < NIT2) { loadAll(it + 2, (it + 2) % 3); cp_commit(); }
        const uint32_t aB = sbase + stg * ST2;
        const uint32_t bB = aB + TILE_B;
#pragma unroll
        for (int kk = 0; kk < 4; kk++) {
            const uint32_t ach = ((kk * 2 + a_c) ^ a_x) * 16;
            const uint32_t bch = ((kk * 2 + b_c) ^ a_x) * 16;
            uint32_t af[4][4];
#pragma unroll
            for (int mi = 0; mi < 4; mi++)
                ldm_x4(af[mi], aB + a_roff + mi * 2048 + ach);
#pragma unroll
            for (int ni = 0; ni < 4; ni++) {
                uint32_t bf[2];
                ldm_x2(bf, bB + b_roff + ni * 1024 + bch);
#pragma unroll
                for (int mi = 0; mi < 4; mi++) mma_f16(acc[mi][ni], af[mi], bf);
            }
        }
    }

    // epilogue: scatter-add with gate coefficient
#pragma unroll
    for (int mi = 0; mi < 4; mi++) {
#pragma unroll
        for (int rh = 0; rh < 2; rh++) {
            const int rr = m0 + wm * 64 + mi * 16 + g + rh * 8;
            if (rr >= rows) continue;
            const int   tok = (z < NE) ? g_perm[segoff + rr] : rr;
            const float cf  = (z < NE) ? g_coef[segoff + rr] : 1.f;
            float* orow = out + (size_t)tok * DIM;
#pragma unroll
            for (int ni = 0; ni < 4; ni++) {
                const int c = n0 + wn * 32 + ni * 8 + 2 * tg;
                atomicAdd(&orow[c],     cf * acc[mi][ni][rh * 2]);
                atomicAdd(&orow[c + 1], cf * acc[mi][ni][rh * 2 + 1]);
            }
        }
    }
}

// ---------------- launcher -------------------------------------------------------------------
extern "C" void kernel_launch(void* const* d_in, const int* in_sizes, int n_in,
                              void* d_out, int out_size) {
    const float* x   = (const float*)d_in[0];
    const float* gw  = (const float*)d_in[1];
    const float* w1  = (const float*)d_in[2];
    const float* w2  = (const float*)d_in[3];
    const float* w3  = (const float*)d_in[4];
    const float* sw1 = (const float*)d_in[5];
    const float* sw2 = (const float*)d_in[6];
    const float* sw3 = (const float*)d_in[7];
    float* out = (float*)d_out;

    cudaFuncSetAttribute(ffn1_kernel, cudaFuncAttributeMaxDynamicSharedMemorySize, SMEM1);
    cudaFuncSetAttribute(ffn2_kernel, cudaFuncAttributeMaxDynamicSharedMemorySize, SMEM2);

    CvtArgs ca;
    void* p;
    cudaGetSymbolAddress(&p, g_xh);   ca.dst[0] = (uint2*)p; ca.src[0] = (const float4*)x;   ca.n4[0] = (T_TOK * DIM) / 4;
    cudaGetSymbolAddress(&p, g_w1h);  ca.dst[1] = (uint2*)p; ca.src[1] = (const float4*)w1;  ca.n4[1] = (NE * HID * DIM) / 4;
    cudaGetSymbolAddress(&p, g_w2h);  ca.dst[2] = (uint2*)p; ca.src[2] = (const float4*)w2;  ca.n4[2] = (NE * DIM * HID) / 4;
    cudaGetSymbolAddress(&p, g_w3h);  ca.dst[3] = (uint2*)p; ca.src[3] = (const float4*)w3;  ca.n4[3] = (NE * HID * DIM) / 4;
    cudaGetSymbolAddress(&p, g_sw1h); ca.dst[4] = (uint2*)p; ca.src[4] = (const float4*)sw1; ca.n4[4] = (HID * DIM) / 4;
    cudaGetSymbolAddress(&p, g_sw2h); ca.dst[5] = (uint2*)p; ca.src[5] = (const float4*)sw2; ca.n4[5] = (DIM * HID) / 4;
    cudaGetSymbolAddress(&p, g_sw3h); ca.dst[6] = (uint2*)p; ca.src[6] = (const float4*)sw3; ca.n4[6] = (HID * DIM) / 4;

    // launch order keeps ffn1 as the 6th launch (ncu -s 5 -c 1 profiles it)
    zero_kernel<<<2048, 256>>>(out);                 // 1
    cvt_all_kernel<<<4096, 256>>>(ca);               // 2
    gate_kernel<<<T_TOK / 8, 256>>>(x, gw);          // 3
    scan_kernel<<<1, 32>>>();                        // 4
    scatter_kernel<<<T_TOK / 256, 256>>>();          // 5

    dim3 g1(NT1, T_TOK / BM, NE + 1);
    ffn1_kernel<<<g1, 256, SMEM1>>>();               // 6  <-- profiled
    dim3 g2(NT2, T_TOK / BM, NE + 1);
    ffn2_kernel<<<g2, 256, SMEM2>>>(out);            // 7
}

// round 6
// speedup vs baseline: 2.1451x; 1.0125x over previous
#include <cuda_runtime.h>
#include <cuda_fp16.h>
#include <cstdint>

#define T_TOK 8192
#define DIM   1024
#define HID   2752
#define NE    8
#define TOPK  2

#define BM 128
#define BN 128
#define BK 64                            // halves per k-iter (128B rows)
#define TILE_B (BM * 128)                // 16384 B per matrix tile
#define ST1 (3 * TILE_B)                 // ffn1 stage: A + B1 + B3 = 49152 B
#define ST2 (2 * TILE_B)                 // ffn2 stage: A + B = 32768 B
#define SMEM1 (3 * ST1 + 512)            // 3-stage + token list
#define SMEM2 (3 * ST2)

#define NT1 ((HID + BN - 1) / BN)        // 22
#define NT2 (DIM / BN)                   // 8
#define NIT1 (DIM / BK)                  // 16
#define NIT2 (HID / BK)                  // 43

#define SWZ(r, c) ((r) * 128 + ((((c) ^ ((r) & 7))) * 16))

// ---------------- device scratch ------------------------------------------------
__device__ int   g_counts[NE];
__device__ int   g_offsets[NE + 1];
__device__ int   g_fill[NE];
__device__ int   g_topk_idx[T_TOK * TOPK];
__device__ float g_topk_w[T_TOK * TOPK];
__device__ int   g_perm[T_TOK * TOPK];
__device__ float g_coef[T_TOK * TOPK];
__device__ __half g_xh[(size_t)T_TOK * DIM];
__device__ __half g_w1h[(size_t)NE * HID * DIM];
__device__ __half g_w3h[(size_t)NE * HID * DIM];
__device__ __half g_w2h[(size_t)NE * DIM * HID];
__device__ __half g_sw1h[(size_t)HID * DIM];
__device__ __half g_sw3h[(size_t)HID * DIM];
__device__ __half g_sw2h[(size_t)DIM * HID];
__device__ __half g_h[(size_t)(T_TOK * TOPK + T_TOK) * HID];

// ---------------- helpers --------------------------------------------------------
__device__ __forceinline__ uint32_t smem_u32(const void* p) {
    return (uint32_t)__cvta_generic_to_shared(p);
}
__device__ __forceinline__ void cp16(uint32_t dst, const void* src) {
    asm volatile("cp.async.cg.shared.global [%0], [%1], 16;\n" :: "r"(dst), "l"(src));
}
__device__ __forceinline__ void cp_commit() { asm volatile("cp.async.commit_group;\n"); }
template <int N>
__device__ __forceinline__ void cp_wait() { asm volatile("cp.async.wait_group %0;\n" :: "n"(N)); }

__device__ __forceinline__ void ldm_x4(uint32_t* r, uint32_t addr) {
    asm volatile("ldmatrix.sync.aligned.m8n8.x4.shared.b16 {%0,%1,%2,%3}, [%4];"
                 : "=r"(r[0]), "=r"(r[1]), "=r"(r[2]), "=r"(r[3]) : "r"(addr));
}
__device__ __forceinline__ void ldm_x2(uint32_t* r, uint32_t addr) {
    asm volatile("ldmatrix.sync.aligned.m8n8.x2.shared.b16 {%0,%1}, [%2];"
                 : "=r"(r[0]), "=r"(r[1]) : "r"(addr));
}
__device__ __forceinline__ void mma_f16(float* d, const uint32_t* a, const uint32_t* b) {
    asm volatile(
        "mma.sync.aligned.m16n8k16.row.col.f32.f16.f16.f32 "
        "{%0,%1,%2,%3},{%4,%5,%6,%7},{%8,%9},{%0,%1,%2,%3};\n"
        : "+f"(d[0]), "+f"(d[1]), "+f"(d[2]), "+f"(d[3])
        : "r"(a[0]), "r"(a[1]), "r"(a[2]), "r"(a[3]), "r"(b[0]), "r"(b[1]));
}

// ---------------- kernel 0: init counters ------------------------------------------
__global__ void init_kernel() {
    if (threadIdx.x < NE) { g_counts[threadIdx.x] = 0; g_fill[threadIdx.x] = 0; }
}

// ---------------- kernel 1: fused convert (7 tensors) + gate ------------------------
struct CvtArgs {
    const float4* src[7];
    uint2*        dst[7];
    int           n4[7];
};
#define GATE_BLKS (T_TOK / 8)   // 1024
#define CVT_BLKS  4096
__global__ void cvt_gate_kernel(CvtArgs a, const float* __restrict__ x,
                                const float* __restrict__ gw) {
    const int bid = blockIdx.x;
    if (bid < GATE_BLKS) {
        // ---- gate: one warp per token ----
        int warp = threadIdx.x >> 5, lane = threadIdx.x & 31;
        int t = bid * 8 + warp;
        const float* xr = x + (size_t)t * DIM;
        float acc[NE];
#pragma unroll
        for (int e = 0; e < NE; e++) acc[e] = 0.f;
        for (int k = lane; k < DIM; k += 32) {
            float xv = xr[k];
#pragma unroll
            for (int e = 0; e < NE; e++) acc[e] += xv * gw[e * DIM + k];
        }
#pragma unroll
        for (int e = 0; e < NE; e++)
#pragma unroll
            for (int o = 16; o > 0; o >>= 1) acc[e] += __shfl_xor_sync(0xffffffffu, acc[e], o);
        if (lane == 0) {
            float mx = acc[0];
#pragma unroll
            for (int e = 1; e < NE; e++) mx = fmaxf(mx, acc[e]);
            float p[NE], s = 0.f;
#pragma unroll
            for (int e = 0; e < NE; e++) { p[e] = expf(acc[e] - mx); s += p[e]; }
            float inv = 1.f / s;
#pragma unroll
            for (int e = 0; e < NE; e++) p[e] *= inv;
            int i0 = 0; float b0 = p[0];
#pragma unroll
            for (int e = 1; e < NE; e++) if (p[e] > b0) { b0 = p[e]; i0 = e; }
            int i1 = -1; float b1 = -1.f;
#pragma unroll
            for (int e = 0; e < NE; e++) if (e != i0 && p[e] > b1) { b1 = p[e]; i1 = e; }
            float wn = 1.f / (b0 + b1 + 1e-20f);
            g_topk_idx[2 * t] = i0;     g_topk_idx[2 * t + 1] = i1;
            g_topk_w[2 * t] = b0 * wn;  g_topk_w[2 * t + 1] = b1 * wn;
            atomicAdd(&g_counts[i0], 1);
            atomicAdd(&g_counts[i1], 1);
        }
        return;
    }
    // ---- convert: f32 -> f16, all 7 tensors ----
    const int stride = CVT_BLKS * blockDim.x;
    const int t0 = (bid - GATE_BLKS) * blockDim.x + threadIdx.x;
#pragma unroll
    for (int s = 0; s < 7; s++) {
        const float4* __restrict__ src = a.src[s];
        uint2* __restrict__ dst = a.dst[s];
        const int n = a.n4[s];
        for (int i = t0; i < n; i += stride) {
            float4 v = src[i];
            __half2 lo = __floats2half2_rn(v.x, v.y);
            __half2 hi = __floats2half2_rn(v.z, v.w);
            uint2 o;
            o.x = *(uint32_t*)&lo;
            o.y = *(uint32_t*)&hi;
            dst[i] = o;
        }
    }
}

// ---------------- kernel 2: scatter (computes offsets locally) ----------------------
__global__ void scatter_kernel() {
    // every block derives offsets from final counts (no separate scan kernel)
    int off[NE];
    {
        int o = 0;
#pragma unroll
        for (int e = 0; e < NE; e++) { off[e] = o; o += g_counts[e]; }
        if (blockIdx.x == 0 && threadIdx.x == 0) {
#pragma unroll
            for (int e = 0; e < NE; e++) g_offsets[e] = off[e];
            g_offsets[NE] = o;
        }
    }
    int t = blockIdx.x * blockDim.x + threadIdx.x;
    if (t >= T_TOK) return;
#pragma unroll
    for (int k = 0; k < TOPK; k++) {
        int e = g_topk_idx[2 * t + k];
        int pos = off[e] + atomicAdd(&g_fill[e], 1);
        g_perm[pos] = t;
        g_coef[pos] = g_topk_w[2 * t + k];
    }
}

// ---------------- kernel 3: FFN1 — h = silu(X W1^T) * (X W3^T) ------------------------
__global__ __launch_bounds__(256, 1) void ffn1_kernel() {
    extern __shared__ char smem[];
    const uint32_t sbase = smem_u32(smem);
    const int z = blockIdx.z;
    const int rows = (z < NE) ? g_counts[z] : T_TOK;
    const int m0 = blockIdx.y * BM;
    if (m0 >= rows) return;
    const int segoff = (z < NE) ? g_offsets[z] : 0;
    const size_t hbase = (z < NE) ? (size_t)g_offsets[z] : (size_t)(T_TOK * TOPK);
    const __half* W1 = (z < NE) ? g_w1h + (size_t)z * HID * DIM : g_sw1h;
    const __half* W3 = (z < NE) ? g_w3h + (size_t)z * HID * DIM : g_sw3h;
    const int n0 = blockIdx.x * BN;
    const int tid = threadIdx.x;

    int* stok = (int*)(smem + 3 * ST1);
    if (tid < BM) {
        int r = m0 + tid;
        int rr = (r < rows) ? r : m0;
        stok[tid] = (z < NE) ? g_perm[segoff + rr] : rr;
    }
    __syncthreads();

    // hoisted, loop-invariant source pointers + swizzled dst offsets
    const __half* aptr[4];
    const __half* b1ptr[4];
    const __half* b3ptr[4];
    uint32_t sdst[4];
#pragma unroll
    for (int i = 0; i < 4; i++) {
        int j = tid + i * 256;
        int r = j >> 3, c8 = j & 7;
        sdst[i] = SWZ(r, c8);
        aptr[i] = g_xh + (size_t)stok[r] * DIM + c8 * 8;
        int nn = n0 + r; if (nn >= HID) nn = HID - 1;
        b1ptr[i] = W1 + (size_t)nn * DIM + c8 * 8;
        b3ptr[i] = W3 + (size_t)nn * DIM + c8 * 8;
    }
    auto loadAll = [&](int it, int stg) {
        const uint32_t base = sbase + stg * ST1;
        const int kt = it * BK;
#pragma unroll
        for (int i = 0; i < 4; i++) {
            cp16(base + sdst[i],              aptr[i] + kt);
            cp16(base + TILE_B + sdst[i],     b1ptr[i] + kt);
            cp16(base + 2 * TILE_B + sdst[i], b3ptr[i] + kt);
        }
    };

    const int lane = tid & 31, wid = tid >> 5;
    const int wm = wid & 1, wn = wid >> 1;        // warp tile 64x32 (x2 matrices)
    const int g = lane >> 2, tg = lane & 3;

    const uint32_t a_roff = (uint32_t)(wm * 64 + (lane & 15)) * 128;
    const uint32_t a_x = lane & 7, a_c = (uint32_t)(lane >> 4);
    const uint32_t b_roff = (uint32_t)(wn * 32 + (lane & 7)) * 128;
    const uint32_t b_c = (uint32_t)((lane >> 3) & 1);

    float accG[4][4][4], accU[4][4][4];
#pragma unroll
    for (int a = 0; a < 4; a++)
#pragma unroll
        for (int b = 0; b < 4; b++)
#pragma unroll
            for (int c = 0; c < 4; c++) { accG[a][b][c] = 0.f; accU[a][b][c] = 0.f; }

    loadAll(0, 0); cp_commit();
    loadAll(1, 1); cp_commit();
    for (int it = 0; it < NIT1; ++it) {
        const int stg = it % 3;
        if (it + 1 < NIT1) cp_wait<1>(); else cp_wait<0>();
        __syncthreads();
        if (it + 2 < NIT1) { loadAll(it + 2, (it + 2) % 3); cp_commit(); }
        const uint32_t aB = sbase + stg * ST1;
        const uint32_t b1B = aB + TILE_B;
        const uint32_t b3B = aB + 2 * TILE_B;
#pragma unroll
        for (int kk = 0; kk < 4; kk++) {
            const uint32_t ach = ((kk * 2 + a_c) ^ a_x) * 16;
            const uint32_t bch = ((kk * 2 + b_c) ^ a_x) * 16;
            uint32_t af[4][4];
#pragma unroll
            for (int mi = 0; mi < 4; mi++)
                ldm_x4(af[mi], aB + a_roff + mi * 2048 + ach);
#pragma unroll
            for (int ni = 0; ni < 4; ni++) {
                uint32_t b1[2], b3[2];
                ldm_x2(b1, b1B + b_roff + ni * 1024 + bch);
                ldm_x2(b3, b3B + b_roff + ni * 1024 + bch);
#pragma unroll
                for (int mi = 0; mi < 4; mi++) {
                    mma_f16(accG[mi][ni], af[mi], b1);
                    mma_f16(accU[mi][ni], af[mi], b3);
                }
            }
        }
    }

    // epilogue: silu(g)*u -> g_h (fp16)
#pragma unroll
    for (int mi = 0; mi < 4; mi++) {
#pragma unroll
        for (int rh = 0; rh < 2; rh++) {
            const int rr = m0 + wm * 64 + mi * 16 + g + rh * 8;
            if (rr >= rows) continue;
            __half* hrow = g_h + (hbase + rr) * (size_t)HID;
#pragma unroll
            for (int ni = 0; ni < 4; ni++) {
                const int c = n0 + wn * 32 + ni * 8 + 2 * tg;
                if (c >= HID) continue;
                float gv0 = accG[mi][ni][rh * 2],     uv0 = accU[mi][ni][rh * 2];
                float gv1 = accG[mi][ni][rh * 2 + 1], uv1 = accU[mi][ni][rh * 2 + 1];
                float h0 = gv0 / (1.f + expf(-gv0)) * uv0;
                float h1 = gv1 / (1.f + expf(-gv1)) * uv1;
                __half2 hv = __floats2half2_rn(h0, h1);
                *(uint32_t*)(hrow + c) = *(uint32_t*)&hv;
            }
        }
    }
}

// ---------------- kernels 4/5: FFN2 — out (+)= coef * (h W2^T) --------------------------
// SHARED=true: shared expert, full coverage, PLAIN STORES (no zero pass needed).
// SHARED=false: routed experts, atomicAdd on top.
template <bool SHARED>
__global__ __launch_bounds__(256, 2) void ffn2_kernel(float* __restrict__ out) {
    extern __shared__ char smem[];
    const uint32_t sbase = smem_u32(smem);
    const int z = SHARED ? NE : blockIdx.z;
    const int rows = SHARED ? T_TOK : g_counts[z];
    const int m0 = blockIdx.y * BM;
    if (m0 >= rows) return;
    const int segoff = SHARED ? 0 : g_offsets[z];
    const size_t hbase = SHARED ? (size_t)(T_TOK * TOPK) : (size_t)g_offsets[z];
    const __half* W2 = SHARED ? g_sw2h : g_w2h + (size_t)z * DIM * HID;
    const int n0 = blockIdx.x * BN;
    const int tid = threadIdx.x;

    const __half* aptr[4];
    const __half* bptr[4];
    uint32_t sdst[4];
#pragma unroll
    for (int i = 0; i < 4; i++) {
        int j = tid + i * 256;
        int r = j >> 3, c8 = j & 7;
        sdst[i] = SWZ(r, c8);
        int rr = (m0 + r < rows) ? (m0 + r) : m0;
        aptr[i] = g_h + (hbase + rr) * (size_t)HID + c8 * 8;
        bptr[i] = W2 + (size_t)(n0 + r) * HID + c8 * 8;
    }
    auto loadAll = [&](int it, int stg) {
        const uint32_t base = sbase + stg * ST2;
        const int kt = it * BK;
#pragma unroll
        for (int i = 0; i < 4; i++) {
            cp16(base + sdst[i],          aptr[i] + kt);
            cp16(base + TILE_B + sdst[i], bptr[i] + kt);
        }
    };

    const int lane = tid & 31, wid = tid >> 5;
    const int wm = wid & 1, wn = wid >> 1;
    const int g = lane >> 2, tg = lane & 3;

    const uint32_t a_roff = (uint32_t)(wm * 64 + (lane & 15)) * 128;
    const uint32_t a_x = lane & 7, a_c = (uint32_t)(lane >> 4);
    const uint32_t b_roff = (uint32_t)(wn * 32 + (lane & 7)) * 128;
    const uint32_t b_c = (uint32_t)((lane >> 3) & 1);

    float acc[4][4][4];
#pragma unroll
    for (int a = 0; a < 4; a++)
#pragma unroll
        for (int b = 0; b < 4; b++)
#pragma unroll
            for (int c = 0; c < 4; c++) acc[a][b][c] = 0.f;

    loadAll(0, 0); cp_commit();
    loadAll(1, 1); cp_commit();
    for (int it = 0; it < NIT2; ++it) {
        const int stg = it % 3;
        if (it + 1 < NIT2) cp_wait<1>(); else cp_wait<0>();
        __syncthreads();
        if (it + 2 < NIT2) { loadAll(it + 2, (it + 2) % 3); cp_commit(); }
        const uint32_t aB = sbase + stg * ST2;
        const uint32_t bB = aB + TILE_B;
#pragma unroll
        for (int kk = 0; kk < 4; kk++) {
            const uint32_t ach = ((kk * 2 + a_c) ^ a_x) * 16;
            const uint32_t bch = ((kk * 2 + b_c) ^ a_x) * 16;
            uint32_t af[4][4];
#pragma unroll
            for (int mi = 0; mi < 4; mi++)
                ldm_x4(af[mi], aB + a_roff + mi * 2048 + ach);
#pragma unroll
            for (int ni = 0; ni < 4; ni++) {
                uint32_t bf[2];
                ldm_x2(bf, bB + b_roff + ni * 1024 + bch);
#pragma unroll
                for (int mi = 0; mi < 4; mi++) mma_f16(acc[mi][ni], af[mi], bf);
            }
        }
    }

    // epilogue
#pragma unroll
    for (int mi = 0; mi < 4; mi++) {
#pragma unroll
        for (int rh = 0; rh < 2; rh++) {
            const int rr = m0 + wm * 64 + mi * 16 + g + rh * 8;
            if (!SHARED && rr >= rows) continue;
            const int   tok = SHARED ? rr : g_perm[segoff + rr];
            const float cf  = SHARED ? 1.f : g_coef[segoff + rr];
            float* orow = out + (size_t)tok * DIM;
#pragma unroll
            for (int ni = 0; ni < 4; ni++) {
                const int c = n0 + wn * 32 + ni * 8 + 2 * tg;
                if (SHARED) {
                    orow[c]     = acc[mi][ni][rh * 2];
                    orow[c + 1] = acc[mi][ni][rh * 2 + 1];
                } else {
                    atomicAdd(&orow[c],     cf * acc[mi][ni][rh * 2]);
                    atomicAdd(&orow[c + 1], cf * acc[mi][ni][rh * 2 + 1]);
                }
            }
        }
    }
}

// ---------------- launcher -------------------------------------------------------------------
extern "C" void kernel_launch(void* const* d_in, const int* in_sizes, int n_in,
                              void* d_out, int out_size) {
    const float* x   = (const float*)d_in[0];
    const float* gw  = (const float*)d_in[1];
    const float* w1  = (const float*)d_in[2];
    const float* w2  = (const float*)d_in[3];
    const float* w3  = (const float*)d_in[4];
    const float* sw1 = (const float*)d_in[5];
    const float* sw2 = (const float*)d_in[6];
    const float* sw3 = (const float*)d_in[7];
    float* out = (float*)d_out;

    cudaFuncSetAttribute(ffn1_kernel, cudaFuncAttributeMaxDynamicSharedMemorySize, SMEM1);
    cudaFuncSetAttribute(ffn2_kernel<true>, cudaFuncAttributeMaxDynamicSharedMemorySize, SMEM2);
    cudaFuncSetAttribute(ffn2_kernel<false>, cudaFuncAttributeMaxDynamicSharedMemorySize, SMEM2);

    CvtArgs ca;
    void* p;
    cudaGetSymbolAddress(&p, g_xh);   ca.dst[0] = (uint2*)p; ca.src[0] = (const float4*)x;   ca.n4[0] = (T_TOK * DIM) / 4;
    cudaGetSymbolAddress(&p, g_w1h);  ca.dst[1] = (uint2*)p; ca.src[1] = (const float4*)w1;  ca.n4[1] = (NE * HID * DIM) / 4;
    cudaGetSymbolAddress(&p, g_w2h);  ca.dst[2] = (uint2*)p; ca.src[2] = (const float4*)w2;  ca.n4[2] = (NE * DIM * HID) / 4;
    cudaGetSymbolAddress(&p, g_w3h);  ca.dst[3] = (uint2*)p; ca.src[3] = (const float4*)w3;  ca.n4[3] = (NE * HID * DIM) / 4;
    cudaGetSymbolAddress(&p, g_sw1h); ca.dst[4] = (uint2*)p; ca.src[4] = (const float4*)sw1; ca.n4[4] = (HID * DIM) / 4;
    cudaGetSymbolAddress(&p, g_sw2h); ca.dst[5] = (uint2*)p; ca.src[5] = (const float4*)sw2; ca.n4[5] = (DIM * HID) / 4;
    cudaGetSymbolAddress(&p, g_sw3h); ca.dst[6] = (uint2*)p; ca.src[6] = (const float4*)sw3; ca.n4[6] = (HID * DIM) / 4;

    init_kernel<<<1, 32>>>();                                  // 1
    cvt_gate_kernel<<<GATE_BLKS + CVT_BLKS, 256>>>(ca, x, gw); // 2
    scatter_kernel<<<T_TOK / 256, 256>>>();                    // 3

    dim3 g1(NT1, T_TOK / BM, NE + 1);
    ffn1_kernel<<<g1, 256, SMEM1>>>();                         // 4
    dim3 g2s(NT2, T_TOK / BM, 1);
    ffn2_kernel<true><<<g2s, 256, SMEM2>>>(out);               // 5 (plain stores)
    dim3 g2r(NT2, T_TOK / BM, NE);
    ffn2_kernel<false><<<g2r, 256, SMEM2>>>(out);              // 6 (atomics) <-- profiled
}